// round 1
// baseline (speedup 1.0000x reference)
#include <cuda_runtime.h>
#include <cstdint>
#include <cstddef>

#define D   64
#define AD  32
#define NN_MAX 100000

// Scratch (no allocs allowed): aggregation buffer + precomputed P = W1 @ Ws_attn
__device__ float g_agg[NN_MAX * D];
__device__ float g_P[D * AD];

// ---------------- f32x2 helpers (packed fp32 SIMD, Blackwell) ----------------
__device__ __forceinline__ unsigned long long pk2(float x, float y) {
    unsigned long long r;
    asm("mov.b64 %0, {%1,%2};" : "=l"(r) : "f"(x), "f"(y));
    return r;
}
__device__ __forceinline__ unsigned long long dup2(float x) {
    unsigned long long r;
    asm("mov.b64 %0, {%1,%1};" : "=l"(r) : "f"(x));
    return r;
}
__device__ __forceinline__ void up2(unsigned long long v, float &x, float &y) {
    asm("mov.b64 {%0,%1}, %2;" : "=f"(x), "=f"(y) : "l"(v));
}
__device__ __forceinline__ unsigned long long ffma2(unsigned long long a,
                                                    unsigned long long b,
                                                    unsigned long long c) {
    unsigned long long d;
    asm("fma.rn.f32x2 %0, %1, %2, %3;" : "=l"(d) : "l"(a), "l"(b), "l"(c));
    return d;
}
__device__ __forceinline__ void red2(float *p, float x, float y) {
    asm volatile("red.global.add.v2.f32 [%0], {%1,%2};"
                 :: "l"(p), "f"(x), "f"(y) : "memory");
}

// ---------------- prep: P = W1 @ Ws_attn  [64,32] ----------------
__global__ void prep_kernel(const float *__restrict__ W1,
                            const float *__restrict__ Ws) {
    int t = blockIdx.x * blockDim.x + threadIdx.x;
    if (t < D * AD) {
        int k = t / AD, j = t % AD;
        float acc = 0.f;
#pragma unroll
        for (int i = 0; i < D; i++) acc += W1[k * D + i] * Ws[i * AD + j];
        g_P[k * AD + j] = acc;
    }
}

// ---------------- zero the aggregation buffer ----------------
__global__ void zero_kernel(int n4) {
    float4 z = make_float4(0.f, 0.f, 0.f, 0.f);
    for (int i = blockIdx.x * blockDim.x + threadIdx.x; i < n4;
         i += gridDim.x * blockDim.x)
        reinterpret_cast<float4 *>(g_agg)[i] = z;
}

// ---------------- main per-edge kernel ----------------
// Each warp: 8 edges/iter. s stored transposed [k][e] (pad 12) so edge-pairs
// pack into f32x2 lanes. W1 columns pre-interleaved {j, j+32} in smem so one
// LDS.64 + 2 dup-movs feed 8 FFMA2 per k. Attention uses P (=W1@Ws_attn).
__global__ __launch_bounds__(192) void edge_kernel(
    const float *__restrict__ hidden, const float *__restrict__ h_sub,
    const float *__restrict__ rela, const float *__restrict__ W1,
    const float *__restrict__ w_alpha, const float *__restrict__ w_b,
    const int *__restrict__ edges, float *__restrict__ alpha_out, int n_edge) {

    __shared__ __align__(16) float W1s[D * D];   // interleaved column pairs
    __shared__ __align__(16) float Ps[D * AD];
    __shared__ __align__(16) float sbuf[6 * 768];
    __shared__ float was[AD];

    for (int i = threadIdx.x; i < 2048; i += blockDim.x) {
        int k = i >> 5, l = i & 31;
        W1s[k * D + 2 * l]     = W1[k * D + l];
        W1s[k * D + 2 * l + 1] = W1[k * D + l + 32];
    }
    for (int i = threadIdx.x; i < D * AD; i += blockDim.x) Ps[i] = g_P[i];
    if (threadIdx.x < AD) was[threadIdx.x] = w_alpha[threadIdx.x];
    __syncthreads();

    const float bb = __ldg(w_b);
    const int lane = threadIdx.x & 31, warp = threadIdx.x >> 5;
    float *st = sbuf + warp * 768;

    const int n_iter = (n_edge + 7) >> 3;
    const int wtot = gridDim.x * 6;
    for (int it = blockIdx.x * 6 + warp; it < n_iter; it += wtot) {
        const int base = it << 3;
        int nv = n_edge - base; if (nv > 8) nv = 8;

        int rel = 0, sub = 0, obj = 0;
        if (lane < nv) {
            const int *ep = edges + (size_t)(base + lane) * 6;
            rel = ep[2]; sub = ep[4]; obj = ep[5];
        }
        // gather + transpose s into smem: st[k*12 + e]
#pragma unroll
        for (int e = 0; e < 8; e++) {
            int se = __shfl_sync(0xffffffffu, sub, e);
            int re = __shfl_sync(0xffffffffu, rel, e);
            float sx = 0.f, sy = 0.f;
            if (e < nv) {
                float2 hs = *(const float2 *)(hidden + (size_t)se * D + 2 * lane);
                float2 hr = *(const float2 *)(rela + (size_t)re * D + 2 * lane);
                float2 hb = *(const float2 *)(h_sub + (size_t)(base + e) * D + 2 * lane);
                sx = hs.x + hr.x + hb.x;
                sy = hs.y + hr.y + hb.y;
            }
            st[(2 * lane) * 12 + e]     = sx;
            st[(2 * lane + 1) * 12 + e] = sy;
        }
        __syncwarp();

        unsigned long long macc[8], tacc[4];
#pragma unroll
        for (int i = 0; i < 8; i++) macc[i] = 0ull;
#pragma unroll
        for (int i = 0; i < 4; i++) tacc[i] = 0ull;

#pragma unroll 16
        for (int k = 0; k < D; k++) {
            float4 sA = *(const float4 *)(st + k * 12);
            float4 sB = *(const float4 *)(st + k * 12 + 4);
            float2 w  = *(const float2 *)(W1s + k * D + 2 * lane);
            float  p  = Ps[k * AD + lane];
            unsigned long long wd0 = dup2(w.x), wd1 = dup2(w.y), pd = dup2(p);
            unsigned long long s01 = pk2(sA.x, sA.y), s23 = pk2(sA.z, sA.w);
            unsigned long long s45 = pk2(sB.x, sB.y), s67 = pk2(sB.z, sB.w);
            macc[0] = ffma2(s01, wd0, macc[0]);
            macc[1] = ffma2(s01, wd1, macc[1]);
            macc[2] = ffma2(s23, wd0, macc[2]);
            macc[3] = ffma2(s23, wd1, macc[3]);
            macc[4] = ffma2(s45, wd0, macc[4]);
            macc[5] = ffma2(s45, wd1, macc[5]);
            macc[6] = ffma2(s67, wd0, macc[6]);
            macc[7] = ffma2(s67, wd1, macc[7]);
            tacc[0] = ffma2(s01, pd, tacc[0]);
            tacc[1] = ffma2(s23, pd, tacc[1]);
            tacc[2] = ffma2(s45, pd, tacc[2]);
            tacc[3] = ffma2(s67, pd, tacc[3]);
        }

        // attention: t_e[j=lane] -> alpha_e (butterfly reduce, per edge pair)
        const float wa = was[lane];
        float a[8];
#pragma unroll
        for (int ep = 0; ep < 4; ep++) {
            float tx, ty;
            up2(tacc[ep], tx, ty);
            tx = fmaxf(tx, 0.f) * wa;
            ty = fmaxf(ty, 0.f) * wa;
#pragma unroll
            for (int off = 16; off > 0; off >>= 1) {
                tx += __shfl_xor_sync(0xffffffffu, tx, off);
                ty += __shfl_xor_sync(0xffffffffu, ty, off);
            }
            a[2 * ep]     = 1.f / (1.f + __expf(-(tx + bb)));
            a[2 * ep + 1] = 1.f / (1.f + __expf(-(ty + bb)));
        }
        __syncwarp();   // k-loop reads of st done before overwrite

        // scale by alpha, transpose through smem: st[e*68 + j]
#pragma unroll
        for (int ep = 0; ep < 4; ep++) {
            const int e0 = 2 * ep, e1 = 2 * ep + 1;
            float v0, v1, u0, u1;
            up2(macc[2 * ep], v0, v1);
            up2(macc[2 * ep + 1], u0, u1);
            st[e0 * 68 + lane]      = v0 * a[e0];
            st[e1 * 68 + lane]      = v1 * a[e1];
            st[e0 * 68 + lane + 32] = u0 * a[e0];
            st[e1 * 68 + lane + 32] = u1 * a[e1];
        }
        __syncwarp();

        // vector-red scatter into g_agg
#pragma unroll
        for (int e = 0; e < 8; e++) {
            if (e < nv) {
                int oe = __shfl_sync(0xffffffffu, obj, e);
                float2 v = *(const float2 *)(st + e * 68 + 2 * lane);
                red2(g_agg + (size_t)oe * D + 2 * lane, v.x, v.y);
            }
        }
        if (lane == 0) {
#pragma unroll
            for (int e = 0; e < 8; e++)
                if (e < nv) alpha_out[base + e] = a[e];
        }
        __syncwarp();
    }
}

// ---------------- final: hidden_new = relu(agg @ W_h) ----------------
__global__ __launch_bounds__(192) void out_kernel(const float *__restrict__ Wh,
                                                  float *__restrict__ out,
                                                  int n_node) {
    __shared__ __align__(16) float Whs[D * D];
    __shared__ __align__(16) float sbuf[6 * 768];

    for (int i = threadIdx.x; i < 2048; i += blockDim.x) {
        int k = i >> 5, l = i & 31;
        Whs[k * D + 2 * l]     = Wh[k * D + l];
        Whs[k * D + 2 * l + 1] = Wh[k * D + l + 32];
    }
    __syncthreads();

    const int lane = threadIdx.x & 31, warp = threadIdx.x >> 5;
    float *st = sbuf + warp * 768;
    const int n_iter = (n_node + 7) >> 3;
    const int wtot = gridDim.x * 6;
    for (int it = blockIdx.x * 6 + warp; it < n_iter; it += wtot) {
        const int base = it << 3;
        int nv = n_node - base; if (nv > 8) nv = 8;
#pragma unroll
        for (int e = 0; e < 8; e++) {
            float2 v = make_float2(0.f, 0.f);
            if (e < nv)
                v = *(const float2 *)(g_agg + (size_t)(base + e) * D + 2 * lane);
            st[(2 * lane) * 12 + e]     = v.x;
            st[(2 * lane + 1) * 12 + e] = v.y;
        }
        __syncwarp();

        unsigned long long macc[8];
#pragma unroll
        for (int i = 0; i < 8; i++) macc[i] = 0ull;
#pragma unroll 16
        for (int k = 0; k < D; k++) {
            float4 sA = *(const float4 *)(st + k * 12);
            float4 sB = *(const float4 *)(st + k * 12 + 4);
            float2 w  = *(const float2 *)(Whs + k * D + 2 * lane);
            unsigned long long wd0 = dup2(w.x), wd1 = dup2(w.y);
            unsigned long long s01 = pk2(sA.x, sA.y), s23 = pk2(sA.z, sA.w);
            unsigned long long s45 = pk2(sB.x, sB.y), s67 = pk2(sB.z, sB.w);
            macc[0] = ffma2(s01, wd0, macc[0]);
            macc[1] = ffma2(s01, wd1, macc[1]);
            macc[2] = ffma2(s23, wd0, macc[2]);
            macc[3] = ffma2(s23, wd1, macc[3]);
            macc[4] = ffma2(s45, wd0, macc[4]);
            macc[5] = ffma2(s45, wd1, macc[5]);
            macc[6] = ffma2(s67, wd0, macc[6]);
            macc[7] = ffma2(s67, wd1, macc[7]);
        }
#pragma unroll
        for (int ep = 0; ep < 4; ep++) {
            float v0, v1, u0, u1;
            up2(macc[2 * ep], v0, v1);
            up2(macc[2 * ep + 1], u0, u1);
            int r0 = base + 2 * ep, r1 = base + 2 * ep + 1;
            if (2 * ep < nv) {
                out[(size_t)r0 * D + lane]      = fmaxf(v0, 0.f);
                out[(size_t)r0 * D + lane + 32] = fmaxf(u0, 0.f);
            }
            if (2 * ep + 1 < nv) {
                out[(size_t)r1 * D + lane]      = fmaxf(v1, 0.f);
                out[(size_t)r1 * D + lane + 32] = fmaxf(u1, 0.f);
            }
        }
        __syncwarp();
    }
}

extern "C" void kernel_launch(void *const *d_in, const int *in_sizes, int n_in,
                              void *d_out, int out_size) {
    const float *hidden = (const float *)d_in[0];
    const float *h_sub  = (const float *)d_in[1];
    const float *rela   = (const float *)d_in[2];
    const float *W1     = (const float *)d_in[3];
    const float *Wsat   = (const float *)d_in[4];
    const float *w_aw   = (const float *)d_in[5];
    const float *w_ab   = (const float *)d_in[6];
    const float *Wh     = (const float *)d_in[7];
    const int   *edges  = (const int *)d_in[8];

    const int n_node = in_sizes[0] / D;   // 100000
    const int n_edge = in_sizes[1] / D;   // 1280000

    float *out = (float *)d_out;                       // hidden_new [n_node, 64]
    float *alpha_out = out + (size_t)n_node * D;       // alpha [n_edge]

    prep_kernel<<<8, 256>>>(W1, Wsat);
    zero_kernel<<<256, 256>>>(n_node * (D / 4));
    edge_kernel<<<740, 192>>>(hidden, h_sub, rela, W1, w_aw, w_ab, edges,
                              alpha_out, n_edge);
    out_kernel<<<740, 192>>>(Wh, out, n_node);
}

// round 5
// speedup vs baseline: 1.7565x; 1.7565x over previous
#include <cuda_runtime.h>
#include <cuda_bf16.h>
#include <cstdint>
#include <cstddef>

#define D   64
#define AD  32
#define NW  96          // combined weight cols: 64 (W1) + 32 (P = W1@Ws_attn)
#define NN_MAX 100000

// ---------------- device scratch (no allocs allowed) ----------------
__device__ float g_agg[NN_MAX * D];
__device__ unsigned short g_Whi[NW * D];   // bf16 bits, [n][k] K-major rows
__device__ unsigned short g_Wlo[NW * D];

// ---------------- helpers ----------------
__device__ __forceinline__ void red2(float *p, float x, float y) {
    asm volatile("red.global.add.v2.f32 [%0], {%1,%2};"
                 :: "l"(p), "f"(x), "f"(y) : "memory");
}
__device__ __forceinline__ unsigned long long pk2(float x, float y) {
    unsigned long long r;
    asm("mov.b64 %0, {%1,%2};" : "=l"(r) : "f"(x), "f"(y));
    return r;
}
__device__ __forceinline__ unsigned long long dup2(float x) {
    unsigned long long r;
    asm("mov.b64 %0, {%1,%1};" : "=l"(r) : "f"(x));
    return r;
}
__device__ __forceinline__ void up2(unsigned long long v, float &x, float &y) {
    asm("mov.b64 {%0,%1}, %2;" : "=f"(x), "=f"(y) : "l"(v));
}
__device__ __forceinline__ unsigned long long ffma2(unsigned long long a,
                                                    unsigned long long b,
                                                    unsigned long long c) {
    unsigned long long d;
    asm("fma.rn.f32x2 %0, %1, %2, %3;" : "=l"(d) : "l"(a), "l"(b), "l"(c));
    return d;
}
__device__ __forceinline__ uint32_t smem_u32(const void *p) {
    uint32_t a;
    asm("{ .reg .u64 t; cvta.to.shared.u64 t, %1; cvt.u32.u64 %0, t; }"
        : "=r"(a) : "l"(p));
    return a;
}
__device__ __forceinline__ void ldsm_x4(uint32_t r[4], uint32_t addr) {
    asm volatile("ldmatrix.sync.aligned.m8n8.x4.shared.b16 {%0,%1,%2,%3}, [%4];"
                 : "=r"(r[0]), "=r"(r[1]), "=r"(r[2]), "=r"(r[3]) : "r"(addr));
}
__device__ __forceinline__ void ldsm_x2(uint32_t r[2], uint32_t addr) {
    asm volatile("ldmatrix.sync.aligned.m8n8.x2.shared.b16 {%0,%1}, [%2];"
                 : "=r"(r[0]), "=r"(r[1]) : "r"(addr));
}
__device__ __forceinline__ void mma_bf16(float c[4], const uint32_t a[4],
                                         const uint32_t b[2]) {
    asm volatile(
        "mma.sync.aligned.m16n8k16.row.col.f32.bf16.bf16.f32 "
        "{%0,%1,%2,%3}, {%4,%5,%6,%7}, {%8,%9}, {%0,%1,%2,%3};"
        : "+f"(c[0]), "+f"(c[1]), "+f"(c[2]), "+f"(c[3])
        : "r"(a[0]), "r"(a[1]), "r"(a[2]), "r"(a[3]), "r"(b[0]), "r"(b[1]));
}

// ---------------- prep: W' = [W1 | W1@Ws_attn] -> [n][k], split bf16 --------
__global__ void prep_kernel(const float *__restrict__ W1,
                            const float *__restrict__ Ws) {
    int t = blockIdx.x * blockDim.x + threadIdx.x;
    if (t >= NW * D) return;
    int n = t / D, k = t % D;
    float v;
    if (n < D) {
        v = W1[k * D + n];
    } else {
        float acc = 0.f;
#pragma unroll
        for (int i = 0; i < D; i++) acc += W1[k * D + i] * Ws[i * AD + (n - D)];
        v = acc;
    }
    __nv_bfloat16 hi = __float2bfloat16(v);
    float resid = v - __bfloat162float(hi);
    __nv_bfloat16 lo = __float2bfloat16(resid);
    g_Whi[t] = __bfloat16_as_ushort(hi);
    g_Wlo[t] = __bfloat16_as_ushort(lo);
}

// ---------------- zero the aggregation buffer ----------------
__global__ void zero_kernel(int n4) {
    float4 z = make_float4(0.f, 0.f, 0.f, 0.f);
    for (int i = blockIdx.x * blockDim.x + threadIdx.x; i < n4;
         i += gridDim.x * blockDim.x)
        reinterpret_cast<float4 *>(g_agg)[i] = z;
}

// ---------------- main: warp-level HMMA edge kernel ----------------
// SMEM: B_hi [96 rows x 128B, chunk-swizzled], B_lo, w_alpha, 8 warp regions
// Warp region (4KB): A_hi [16x128B] + A_lo [16x128B]; aliased by the 16x256B
// f32 message staging after the MMAs.
#define OFF_BHI   0            // 12288
#define OFF_BLO   12288        // 12288
#define OFF_WAS   24576        // 128
#define OFF_WARP  24704        // 8 * 4096
#define WREG      4096
#define SMEM_BYTES (OFF_WARP + 8 * WREG)   // 57472

__global__ __launch_bounds__(256, 2) void edge_hmma_kernel(
    const float *__restrict__ hidden, const float *__restrict__ h_sub,
    const float *__restrict__ rela, const float *__restrict__ w_alpha,
    const float *__restrict__ w_b, const int *__restrict__ edges,
    float *__restrict__ alpha_out, int n_edge) {

    extern __shared__ char smem[];
    const uint32_t sb = smem_u32(smem);
    const int tid = threadIdx.x;
    const int wid = tid >> 5, lane = tid & 31;

    // weights into smem, [n][k] bf16 rows of 128B, 16B-chunk swizzle ^ (n&7)
    for (int i = tid; i < NW * D; i += 256) {
        int n = i >> 6, k = i & 63;
        uint32_t off = (uint32_t)n * 128 + ((((k >> 3) ^ n) & 7) << 4) +
                       (k & 7) * 2;
        *(unsigned short *)(smem + OFF_BHI + off) = g_Whi[i];
        *(unsigned short *)(smem + OFF_BLO + off) = g_Wlo[i];
    }
    if (tid < AD) ((float *)(smem + OFF_WAS))[tid] = w_alpha[tid];
    __syncthreads();

    const float bias = __ldg(w_b);
    char *wreg = smem + OFF_WARP + wid * WREG;
    const uint32_t wreg_u = sb + OFF_WARP + wid * WREG;

    // ldmatrix lane-address components
    const int arow = (lane & 7) + (((lane >> 3) & 1) << 3);   // A matrix row
    const int ahalf = lane >> 4;                              // A k-half
    const int bn = lane & 7;                                  // B n-within-tile
    const int bhalf = (lane >> 3) & 1;                        // B k-half
    const int quad = lane >> 2, qc = (lane & 3) * 2;          // frag coords

    const int n_wt = (n_edge + 15) >> 4;
    const int wstep = gridDim.x * 8;
    for (int wt = blockIdx.x * 8 + wid; wt < n_wt; wt += wstep) {
        const int base = wt << 4;

        int rel = 0, sub = 0, obj = 0;
        if (lane < 16) {
            int ge = base + lane;
            if (ge < n_edge) {
                const int *ep = edges + (size_t)ge * 6;
                rel = ep[2]; sub = ep[4]; obj = ep[5];
            }
        }

        // --- gather + split-bf16 into swizzled A staging ---
#pragma unroll 4
        for (int e = 0; e < 16; e++) {
            int se = __shfl_sync(0xffffffffu, sub, e);
            int re = __shfl_sync(0xffffffffu, rel, e);
            int ge = base + e;
            uint32_t off = (uint32_t)e * 128 +
                           ((((lane >> 2) ^ e) & 7) << 4) + (lane & 3) * 4;
            float s0 = 0.f, s1 = 0.f;
            if (ge < n_edge) {
                float2 hs = *(const float2 *)(hidden + (size_t)se * D + 2 * lane);
                float2 hr = *(const float2 *)(rela + (size_t)re * D + 2 * lane);
                float2 hb = *(const float2 *)(h_sub + (size_t)ge * D + 2 * lane);
                s0 = hs.x + hr.x + hb.x;
                s1 = hs.y + hr.y + hb.y;
            }
            __nv_bfloat16 h0 = __float2bfloat16(s0);
            __nv_bfloat16 h1 = __float2bfloat16(s1);
            __nv_bfloat16 l0 = __float2bfloat16(s0 - __bfloat162float(h0));
            __nv_bfloat16 l1 = __float2bfloat16(s1 - __bfloat162float(h1));
            uint32_t hp = (uint32_t)__bfloat16_as_ushort(h0) |
                          ((uint32_t)__bfloat16_as_ushort(h1) << 16);
            uint32_t lp = (uint32_t)__bfloat16_as_ushort(l0) |
                          ((uint32_t)__bfloat16_as_ushort(l1) << 16);
            *(uint32_t *)(wreg + off) = hp;
            *(uint32_t *)(wreg + 2048 + off) = lp;
        }
        __syncwarp();

        // --- HMMA: C[16,96] = Ah@Bh + Ah@Bl + Al@Bh ---
        float cacc[12][4];
#pragma unroll
        for (int i = 0; i < 12; i++)
#pragma unroll
            for (int j = 0; j < 4; j++) cacc[i][j] = 0.f;

#pragma unroll
        for (int kt = 0; kt < 4; kt++) {
            uint32_t ach = (uint32_t)((2 * kt + ahalf) ^ (arow & 7));
            uint32_t aaddr = wreg_u + (uint32_t)arow * 128 + (ach << 4);
            uint32_t ah[4], al[4];
            ldsm_x4(ah, aaddr);
            ldsm_x4(al, aaddr + 2048);
#pragma unroll
            for (int nt = 0; nt < 12; nt++) {
                uint32_t brow = (uint32_t)(nt * 8 + bn);
                uint32_t bch = (uint32_t)((2 * kt + bhalf) ^ bn);
                uint32_t baddr = sb + OFF_BHI + brow * 128 + (bch << 4);
                uint32_t bh[2], bl[2];
                ldsm_x2(bh, baddr);
                ldsm_x2(bl, baddr + (OFF_BLO - OFF_BHI));
                mma_bf16(cacc[nt], ah, bh);
                mma_bf16(cacc[nt], ah, bl);
                mma_bf16(cacc[nt], al, bh);
            }
        }

        // --- attention: cols 64..95 live in ntiles 8..11, quad-local reduce
        const float *wasp = (const float *)(smem + OFF_WAS);
        float p0 = 0.f, p1 = 0.f;
#pragma unroll
        for (int nt = 8; nt < 12; nt++) {
            float2 wv = *(const float2 *)(wasp + (nt - 8) * 8 + qc);
            p0 += fmaxf(cacc[nt][0], 0.f) * wv.x + fmaxf(cacc[nt][1], 0.f) * wv.y;
            p1 += fmaxf(cacc[nt][2], 0.f) * wv.x + fmaxf(cacc[nt][3], 0.f) * wv.y;
        }
        p0 += __shfl_xor_sync(0xffffffffu, p0, 1);
        p0 += __shfl_xor_sync(0xffffffffu, p0, 2);
        p1 += __shfl_xor_sync(0xffffffffu, p1, 1);
        p1 += __shfl_xor_sync(0xffffffffu, p1, 2);
        float al0 = 1.f / (1.f + __expf(-(p0 + bias)));
        float al1 = 1.f / (1.f + __expf(-(p1 + bias)));
        if ((lane & 3) == 0) {
            if (base + quad < n_edge)     alpha_out[base + quad] = al0;
            if (base + quad + 8 < n_edge) alpha_out[base + quad + 8] = al1;
        }

        // --- stage alpha-scaled messages (aliases A region), swizzled 8B units
        __syncwarp();
#pragma unroll
        for (int nt = 0; nt < 8; nt++) {
            uint32_t u = (uint32_t)(nt * 4 + (lane & 3));
            uint32_t sw = ((u ^ ((quad & 7) << 2)) << 3);
            *(float2 *)(wreg + (uint32_t)quad * 256 + sw) =
                make_float2(cacc[nt][0] * al0, cacc[nt][1] * al0);
            *(float2 *)(wreg + (uint32_t)(quad + 8) * 256 + sw) =
                make_float2(cacc[nt][2] * al1, cacc[nt][3] * al1);
        }
        __syncwarp();

        // --- scatter: per edge, 32 lanes x float2, coalesced red.v2 ---
#pragma unroll 4
        for (int e = 0; e < 16; e++) {
            int oe = __shfl_sync(0xffffffffu, obj, e);
            int ge = base + e;
            if (ge < n_edge) {
                uint32_t off = (uint32_t)e * 256 +
                               (((uint32_t)lane ^ ((e & 7) << 2)) << 3);
                float2 v = *(const float2 *)(wreg + off);
                red2(g_agg + (size_t)oe * D + 2 * lane, v.x, v.y);
            }
        }
        __syncwarp();
    }
}

// ---------------- final: hidden_new = relu(agg @ W_h) (f32x2 path) ----------
__global__ __launch_bounds__(192) void out_kernel(const float *__restrict__ Wh,
                                                  float *__restrict__ out,
                                                  int n_node) {
    __shared__ __align__(16) float Whs[D * D];
    __shared__ __align__(16) float sbuf[6 * 768];

    for (int i = threadIdx.x; i < 2048; i += blockDim.x) {
        int k = i >> 5, l = i & 31;
        Whs[k * D + 2 * l]     = Wh[k * D + l];
        Whs[k * D + 2 * l + 1] = Wh[k * D + l + 32];
    }
    __syncthreads();

    const int lane = threadIdx.x & 31, warp = threadIdx.x >> 5;
    float *st = sbuf + warp * 768;
    const int n_iter = (n_node + 7) >> 3;
    const int wtot = gridDim.x * 6;
    for (int it = blockIdx.x * 6 + warp; it < n_iter; it += wtot) {
        const int base = it << 3;
        int nv = n_node - base; if (nv > 8) nv = 8;
#pragma unroll
        for (int e = 0; e < 8; e++) {
            float2 v = make_float2(0.f, 0.f);
            if (e < nv)
                v = *(const float2 *)(g_agg + (size_t)(base + e) * D + 2 * lane);
            st[(2 * lane) * 12 + e]     = v.x;
            st[(2 * lane + 1) * 12 + e] = v.y;
        }
        __syncwarp();

        unsigned long long macc[8];
#pragma unroll
        for (int i = 0; i < 8; i++) macc[i] = 0ull;
#pragma unroll 16
        for (int k = 0; k < D; k++) {
            float4 sA = *(const float4 *)(st + k * 12);
            float4 sB = *(const float4 *)(st + k * 12 + 4);
            float2 w  = *(const float2 *)(Whs + k * D + 2 * lane);
            unsigned long long wd0 = dup2(w.x), wd1 = dup2(w.y);
            unsigned long long s01 = pk2(sA.x, sA.y), s23 = pk2(sA.z, sA.w);
            unsigned long long s45 = pk2(sB.x, sB.y), s67 = pk2(sB.z, sB.w);
            macc[0] = ffma2(s01, wd0, macc[0]);
            macc[1] = ffma2(s01, wd1, macc[1]);
            macc[2] = ffma2(s23, wd0, macc[2]);
            macc[3] = ffma2(s23, wd1, macc[3]);
            macc[4] = ffma2(s45, wd0, macc[4]);
            macc[5] = ffma2(s45, wd1, macc[5]);
            macc[6] = ffma2(s67, wd0, macc[6]);
            macc[7] = ffma2(s67, wd1, macc[7]);
        }
#pragma unroll
        for (int ep = 0; ep < 4; ep++) {
            float v0, v1, u0, u1;
            up2(macc[2 * ep], v0, v1);
            up2(macc[2 * ep + 1], u0, u1);
            int r0 = base + 2 * ep, r1 = base + 2 * ep + 1;
            if (2 * ep < nv) {
                out[(size_t)r0 * D + lane]      = fmaxf(v0, 0.f);
                out[(size_t)r0 * D + lane + 32] = fmaxf(u0, 0.f);
            }
            if (2 * ep + 1 < nv) {
                out[(size_t)r1 * D + lane]      = fmaxf(v1, 0.f);
                out[(size_t)r1 * D + lane + 32] = fmaxf(u1, 0.f);
            }
        }
        __syncwarp();
    }
}

extern "C" void kernel_launch(void *const *d_in, const int *in_sizes, int n_in,
                              void *d_out, int out_size) {
    const float *hidden = (const float *)d_in[0];
    const float *h_sub  = (const float *)d_in[1];
    const float *rela   = (const float *)d_in[2];
    const float *W1     = (const float *)d_in[3];
    const float *Wsat   = (const float *)d_in[4];
    const float *w_aw   = (const float *)d_in[5];
    const float *w_ab   = (const float *)d_in[6];
    const float *Wh     = (const float *)d_in[7];
    const int   *edges  = (const int *)d_in[8];

    const int n_node = in_sizes[0] / D;   // 100000
    const int n_edge = in_sizes[1] / D;   // 1280000

    float *out = (float *)d_out;                      // hidden_new [n_node, 64]
    float *alpha_out = out + (size_t)n_node * D;      // alpha [n_edge]

    cudaFuncSetAttribute(edge_hmma_kernel,
                         cudaFuncAttributeMaxDynamicSharedMemorySize, SMEM_BYTES);

    prep_kernel<<<24, 256>>>(W1, Wsat);
    zero_kernel<<<256, 256>>>(n_node * (D / 4));
    edge_hmma_kernel<<<296, 256, SMEM_BYTES>>>(hidden, h_sub, rela, w_aw, w_ab,
                                               edges, alpha_out, n_edge);
    out_kernel<<<740, 192>>>(Wh, out, n_node);
}